// round 1
// baseline (speedup 1.0000x reference)
#include <cuda_runtime.h>
#include <cuda_bf16.h>

#define N_NODES 50000
#define N_EDGES 800000
#define D 64
#define BN_EPS 1e-5f

// Scratch (device globals; no allocations allowed).
__device__ float4 g_t[N_NODES * (D/4)];   // t' = (h@W) * dinv[node]
__device__ float4 g_s[N_NODES * (D/4)];   // accumulator (init = t', self-loop)
__device__ float4 g_h[N_NODES * (D/4)];   // layer output
__device__ float  g_deg[N_NODES];
__device__ float  g_dinv[N_NODES];

// ---------------------------------------------------------------------------
// Degree / dinv
// ---------------------------------------------------------------------------
__global__ void deg_init_kernel() {
    int i = blockIdx.x * blockDim.x + threadIdx.x;
    if (i < N_NODES) g_deg[i] = 1.0f;   // self loop
}

__global__ void deg_count_kernel(const int* __restrict__ coli) {
    int e = blockIdx.x * blockDim.x + threadIdx.x;
    if (e < N_EDGES) atomicAdd(&g_deg[coli[e]], 1.0f);
}

__global__ void dinv_kernel() {
    int i = blockIdx.x * blockDim.x + threadIdx.x;
    if (i < N_NODES) g_dinv[i] = rsqrtf(g_deg[i]);
}

// ---------------------------------------------------------------------------
// GEMM: t' = (in @ W) * dinv, also s = t'.
// Block = 256 threads = 16 nodes x 16 feature-groups (4 feats each).
// in == nullptr -> read previous layer output g_h.
// ---------------------------------------------------------------------------
__global__ void gemm_kernel(const float* __restrict__ in,
                            const float* __restrict__ W) {
    __shared__ float4 sW[D * (D/4)];      // 64x64 = 16 KB
    __shared__ float4 sx[16 * (D/4)];     // 16 rows x 64 = 4 KB

    int tid = threadIdx.x;
    int node0 = blockIdx.x * 16;

    // Load W (1024 float4 / 256 threads = 4 each)
    const float4* W4 = (const float4*)W;
    #pragma unroll
    for (int i = 0; i < 4; i++) sW[tid + 256 * i] = W4[tid + 256 * i];

    // Load 16 input rows (256 float4, one per thread), coalesced.
    {
        int r = tid >> 4;            // node within tile
        int c4 = tid & 15;           // float4 within row
        int node = node0 + r;
        float4 v = make_float4(0.f, 0.f, 0.f, 0.f);
        if (node < N_NODES) {
            if (in) v = ((const float4*)in)[node * (D/4) + c4];
            else    v = g_h[node * (D/4) + c4];
        }
        sx[tid] = v;
    }
    __syncthreads();

    int local = tid >> 4;   // node within tile
    int jg    = tid & 15;   // output feature group
    int node  = node0 + local;
    if (node >= N_NODES) return;

    const float* xrow = (const float*)&sx[local * (D/4)];
    float4 acc = make_float4(0.f, 0.f, 0.f, 0.f);
    #pragma unroll
    for (int k = 0; k < D; k++) {
        float xv = xrow[k];
        float4 w = sW[k * (D/4) + jg];
        acc.x += xv * w.x;
        acc.y += xv * w.y;
        acc.z += xv * w.z;
        acc.w += xv * w.w;
    }
    float dv = g_dinv[node];
    acc.x *= dv; acc.y *= dv; acc.z *= dv; acc.w *= dv;
    g_t[node * (D/4) + jg] = acc;
    g_s[node * (D/4) + jg] = acc;   // self-loop term pre-seeded
}

// ---------------------------------------------------------------------------
// Edge scatter: s[col] += t'[row]. 16 threads per edge, 4 floats each.
// ---------------------------------------------------------------------------
__global__ void scatter_kernel(const int* __restrict__ rowi,
                               const int* __restrict__ coli) {
    int t = blockIdx.x * blockDim.x + threadIdx.x;
    int e = t >> 4;
    int lane = t & 15;
    if (e >= N_EDGES) return;
    int r = __ldg(&rowi[e]);
    int c = __ldg(&coli[e]);
    float4 v = g_t[r * (D/4) + lane];
    float* dst = (float*)&g_s[c * (D/4) + lane];
    atomicAdd(dst + 0, v.x);
    atomicAdd(dst + 1, v.y);
    atomicAdd(dst + 2, v.z);
    atomicAdd(dst + 3, v.w);
}

// ---------------------------------------------------------------------------
// Finalize: h = relu( ((s*dinv + b) - mean) * rsqrt(var+eps) * gamma + beta )
// ---------------------------------------------------------------------------
__global__ void finalize_kernel(const float* __restrict__ b,
                                const float* __restrict__ gamma,
                                const float* __restrict__ beta,
                                const float* __restrict__ mean,
                                const float* __restrict__ var) {
    int t = blockIdx.x * blockDim.x + threadIdx.x;
    int node = t >> 4;
    int jg = t & 15;
    if (node >= N_NODES) return;

    float dv = g_dinv[node];
    float4 v  = g_s[node * (D/4) + jg];
    float4 bb = ((const float4*)b)[jg];
    float4 gm = ((const float4*)gamma)[jg];
    float4 bt = ((const float4*)beta)[jg];
    float4 mn = ((const float4*)mean)[jg];
    float4 vr = ((const float4*)var)[jg];

    float4 h;
    h.x = fmaxf(0.f, (v.x * dv + bb.x - mn.x) * rsqrtf(vr.x + BN_EPS) * gm.x + bt.x);
    h.y = fmaxf(0.f, (v.y * dv + bb.y - mn.y) * rsqrtf(vr.y + BN_EPS) * gm.y + bt.y);
    h.z = fmaxf(0.f, (v.z * dv + bb.z - mn.z) * rsqrtf(vr.z + BN_EPS) * gm.z + bt.z);
    h.w = fmaxf(0.f, (v.w * dv + bb.w - mn.w) * rsqrtf(vr.w + BN_EPS) * gm.w + bt.w);
    g_h[node * (D/4) + jg] = h;
}

// ---------------------------------------------------------------------------
// Output head: out[i] = dot(h[i], lin_w) + lin_b. One warp per node.
// ---------------------------------------------------------------------------
__global__ void out_kernel(const float* __restrict__ lin_w,
                           const float* __restrict__ lin_b,
                           float* __restrict__ out) {
    int gt = blockIdx.x * blockDim.x + threadIdx.x;
    int node = gt >> 5;
    int lane = threadIdx.x & 31;
    if (node >= N_NODES) return;
    const float2* h2 = (const float2*)g_h;
    float2 h = h2[node * 32 + lane];
    float2 w = ((const float2*)lin_w)[lane];
    float sum = h.x * w.x + h.y * w.y;
    #pragma unroll
    for (int o = 16; o; o >>= 1) sum += __shfl_xor_sync(0xFFFFFFFFu, sum, o);
    if (lane == 0) out[node] = sum + lin_b[0];
}

// ---------------------------------------------------------------------------
extern "C" void kernel_launch(void* const* d_in, const int* in_sizes, int n_in,
                              void* d_out, int out_size) {
    const float* x        = (const float*)d_in[0];
    const int*   ei       = (const int*)  d_in[1];   // [2, E]
    const float* Ws       = (const float*)d_in[2];   // [3, 64, 64]
    const float* bs       = (const float*)d_in[3];
    const float* gammas   = (const float*)d_in[4];
    const float* betas    = (const float*)d_in[5];
    const float* means    = (const float*)d_in[6];
    const float* variances= (const float*)d_in[7];
    const float* lin_w    = (const float*)d_in[8];
    const float* lin_b    = (const float*)d_in[9];

    const int* rowi = ei;
    const int* coli = ei + N_EDGES;

    deg_init_kernel<<<(N_NODES + 255) / 256, 256>>>();
    deg_count_kernel<<<(N_EDGES + 255) / 256, 256>>>(coli);
    dinv_kernel<<<(N_NODES + 255) / 256, 256>>>();

    const int gemm_blocks = (N_NODES + 15) / 16;
    const long long scatter_threads = (long long)N_EDGES * 16;
    const int scatter_blocks = (int)((scatter_threads + 255) / 256);
    const int fin_blocks = (N_NODES * 16 + 255) / 256;

    for (int l = 0; l < 3; l++) {
        const float* in = (l == 0) ? x : nullptr;   // nullptr -> g_h
        gemm_kernel<<<gemm_blocks, 256>>>(in, Ws + l * D * D);
        scatter_kernel<<<scatter_blocks, 256>>>(rowi, coli);
        finalize_kernel<<<fin_blocks, 256>>>(bs + l * D, gammas + l * D,
                                             betas + l * D, means + l * D,
                                             variances + l * D);
    }

    out_kernel<<<(N_NODES * 32 + 255) / 256, 256>>>(lin_w, lin_b, (float*)d_out);
}

// round 2
// speedup vs baseline: 1.9055x; 1.9055x over previous
#include <cuda_runtime.h>
#include <cuda_bf16.h>

#define N_NODES 50000
#define N_EDGES 800000
#define D 64
#define BN_EPS 1e-5f

// Scratch (device globals; no allocations allowed).
__device__ float4 g_t[N_NODES * (D/4)];   // t' = (h@W) * dinv[node]
__device__ float4 g_s[N_NODES * (D/4)];   // accumulator (init = t', self-loop)
__device__ float4 g_h[N_NODES * (D/4)];   // layer output
__device__ float  g_deg[N_NODES];
__device__ float  g_dinv[N_NODES];

// ---------------------------------------------------------------------------
// Degree / dinv
// ---------------------------------------------------------------------------
__global__ void deg_init_kernel() {
    int i = blockIdx.x * blockDim.x + threadIdx.x;
    if (i < N_NODES) g_deg[i] = 1.0f;   // self loop
}

__global__ void deg_count_kernel(const int* __restrict__ coli) {
    int e = blockIdx.x * blockDim.x + threadIdx.x;
    if (e < N_EDGES) atomicAdd(&g_deg[coli[e]], 1.0f);
}

__global__ void dinv_kernel() {
    int i = blockIdx.x * blockDim.x + threadIdx.x;
    if (i < N_NODES) g_dinv[i] = rsqrtf(g_deg[i]);
}

// ---------------------------------------------------------------------------
// GEMM: t' = (in @ W) * dinv, also s = t'.
// Block = 256 threads, 64-node tile. Thread = (node-quad nq, feature group jg);
// computes 4 nodes x 4 feats -> 16 independent FMA chains.
// in == nullptr -> read previous layer output g_h.
// ---------------------------------------------------------------------------
#define XPAD 68   // floats per padded row (64 + 4) -> conflict-free banks

__global__ __launch_bounds__(256) void gemm_kernel(const float* __restrict__ in,
                                                   const float* __restrict__ W) {
    __shared__ float4 sW[D * (D/4)];      // 64x64 = 16 KB
    __shared__ float  sx[64 * XPAD];      // 64 rows padded, ~17 KB

    int tid = threadIdx.x;
    int node0 = blockIdx.x * 64;

    // Load W (1024 float4 / 256 threads = 4 each)
    const float4* W4 = (const float4*)W;
    #pragma unroll
    for (int i = 0; i < 4; i++) sW[tid + 256 * i] = W4[tid + 256 * i];

    // Load 64 input rows (1024 float4, 4 per thread), coalesced, padded store.
    float4* sx4 = (float4*)sx;
    #pragma unroll
    for (int i = 0; i < 4; i++) {
        int g = tid + 256 * i;
        int r = g >> 4;              // row within tile
        int c4 = g & 15;             // float4 within row
        int node = node0 + r;
        float4 v = make_float4(0.f, 0.f, 0.f, 0.f);
        if (node < N_NODES) {
            if (in) v = ((const float4*)in)[node * (D/4) + c4];
            else    v = g_h[node * (D/4) + c4];
        }
        sx4[r * (XPAD/4) + c4] = v;
    }
    __syncthreads();

    int jg = tid & 15;     // output feature group
    int nq = tid >> 4;     // node quad (0..15)

    float4 acc[4];
    #pragma unroll
    for (int i = 0; i < 4; i++) acc[i] = make_float4(0.f, 0.f, 0.f, 0.f);

    #pragma unroll 8
    for (int k = 0; k < D; k++) {
        float4 w = sW[k * (D/4) + jg];
        #pragma unroll
        for (int i = 0; i < 4; i++) {
            float xv = sx[(nq * 4 + i) * XPAD + k];
            acc[i].x += xv * w.x;
            acc[i].y += xv * w.y;
            acc[i].z += xv * w.z;
            acc[i].w += xv * w.w;
        }
    }

    #pragma unroll
    for (int i = 0; i < 4; i++) {
        int node = node0 + nq * 4 + i;
        if (node < N_NODES) {
            float dv = g_dinv[node];
            float4 a = acc[i];
            a.x *= dv; a.y *= dv; a.z *= dv; a.w *= dv;
            g_t[node * (D/4) + jg] = a;
            g_s[node * (D/4) + jg] = a;   // self-loop term pre-seeded
        }
    }
}

// ---------------------------------------------------------------------------
// Edge scatter: s[col] += t'[row]. 16 threads per edge, one red.v4.f32 each.
// Block of 256 threads handles 16 edges; indices staged via shared memory.
// ---------------------------------------------------------------------------
__global__ __launch_bounds__(256) void scatter_kernel(const int* __restrict__ rowi,
                                                      const int* __restrict__ coli) {
    __shared__ int sr[16];
    __shared__ int sc[16];
    int tid = threadIdx.x;
    int eb = blockIdx.x * 16;

    if (tid < 16) {
        int e = eb + tid;
        sr[tid] = (e < N_EDGES) ? rowi[e] : -1;
    } else if (tid < 32) {
        int e = eb + tid - 16;
        sc[tid - 16] = (e < N_EDGES) ? coli[e] : -1;
    }
    __syncthreads();

    int le = tid >> 4;        // local edge 0..15
    int sub = tid & 15;       // float4 index within row
    int r = sr[le];
    if (r < 0) return;
    int c = sc[le];

    float4 v = g_t[r * (D/4) + sub];
    float4* dst = &g_s[c * (D/4) + sub];
    asm volatile("red.global.add.v4.f32 [%0], {%1, %2, %3, %4};"
                 :: "l"(dst), "f"(v.x), "f"(v.y), "f"(v.z), "f"(v.w)
                 : "memory");
}

// ---------------------------------------------------------------------------
// Finalize: h = relu( ((s*dinv + b) - mean) * rsqrt(var+eps) * gamma + beta )
// ---------------------------------------------------------------------------
__global__ void finalize_kernel(const float* __restrict__ b,
                                const float* __restrict__ gamma,
                                const float* __restrict__ beta,
                                const float* __restrict__ mean,
                                const float* __restrict__ var) {
    int t = blockIdx.x * blockDim.x + threadIdx.x;
    int node = t >> 4;
    int jg = t & 15;
    if (node >= N_NODES) return;

    float dv = g_dinv[node];
    float4 v  = g_s[node * (D/4) + jg];
    float4 bb = ((const float4*)b)[jg];
    float4 gm = ((const float4*)gamma)[jg];
    float4 bt = ((const float4*)beta)[jg];
    float4 mn = ((const float4*)mean)[jg];
    float4 vr = ((const float4*)var)[jg];

    float4 h;
    h.x = fmaxf(0.f, (v.x * dv + bb.x - mn.x) * rsqrtf(vr.x + BN_EPS) * gm.x + bt.x);
    h.y = fmaxf(0.f, (v.y * dv + bb.y - mn.y) * rsqrtf(vr.y + BN_EPS) * gm.y + bt.y);
    h.z = fmaxf(0.f, (v.z * dv + bb.z - mn.z) * rsqrtf(vr.z + BN_EPS) * gm.z + bt.z);
    h.w = fmaxf(0.f, (v.w * dv + bb.w - mn.w) * rsqrtf(vr.w + BN_EPS) * gm.w + bt.w);
    g_h[node * (D/4) + jg] = h;
}

// ---------------------------------------------------------------------------
// Output head: out[i] = dot(h[i], lin_w) + lin_b. One warp per node.
// ---------------------------------------------------------------------------
__global__ void out_kernel(const float* __restrict__ lin_w,
                           const float* __restrict__ lin_b,
                           float* __restrict__ out) {
    int gt = blockIdx.x * blockDim.x + threadIdx.x;
    int node = gt >> 5;
    int lane = threadIdx.x & 31;
    if (node >= N_NODES) return;
    const float2* h2 = (const float2*)g_h;
    float2 h = h2[node * 32 + lane];
    float2 w = ((const float2*)lin_w)[lane];
    float sum = h.x * w.x + h.y * w.y;
    #pragma unroll
    for (int o = 16; o; o >>= 1) sum += __shfl_xor_sync(0xFFFFFFFFu, sum, o);
    if (lane == 0) out[node] = sum + lin_b[0];
}

// ---------------------------------------------------------------------------
extern "C" void kernel_launch(void* const* d_in, const int* in_sizes, int n_in,
                              void* d_out, int out_size) {
    const float* x        = (const float*)d_in[0];
    const int*   ei       = (const int*)  d_in[1];   // [2, E]
    const float* Ws       = (const float*)d_in[2];   // [3, 64, 64]
    const float* bs       = (const float*)d_in[3];
    const float* gammas   = (const float*)d_in[4];
    const float* betas    = (const float*)d_in[5];
    const float* means    = (const float*)d_in[6];
    const float* variances= (const float*)d_in[7];
    const float* lin_w    = (const float*)d_in[8];
    const float* lin_b    = (const float*)d_in[9];

    const int* rowi = ei;
    const int* coli = ei + N_EDGES;

    deg_init_kernel<<<(N_NODES + 255) / 256, 256>>>();
    deg_count_kernel<<<(N_EDGES + 255) / 256, 256>>>(coli);
    dinv_kernel<<<(N_NODES + 255) / 256, 256>>>();

    const int gemm_blocks = (N_NODES + 63) / 64;
    const int scatter_blocks = (N_EDGES + 15) / 16;
    const int fin_blocks = (N_NODES * 16 + 255) / 256;

    for (int l = 0; l < 3; l++) {
        const float* in = (l == 0) ? x : nullptr;   // nullptr -> g_h
        gemm_kernel<<<gemm_blocks, 256>>>(in, Ws + l * D * D);
        scatter_kernel<<<scatter_blocks, 256>>>(rowi, coli);
        finalize_kernel<<<fin_blocks, 256>>>(bs + l * D, gammas + l * D,
                                             betas + l * D, means + l * D,
                                             variances + l * D);
    }

    out_kernel<<<(N_NODES * 32 + 255) / 256, 256>>>(lin_w, lin_b, (float*)d_out);
}

// round 3
// speedup vs baseline: 3.3904x; 1.7792x over previous
#include <cuda_runtime.h>
#include <cuda_bf16.h>

#define N_NODES 50000
#define N_EDGES 800000
#define D 64
#define BN_EPS 1e-5f

#define SCAN_BS 1024                       // elements per scan1 block
#define NB1 ((N_NODES + SCAN_BS - 1) / SCAN_BS)   // 49

// Scratch (device globals; no allocations allowed).
__device__ float4 g_t[N_NODES * (D/4)];    // t' = (h@W) * dinv[node]
__device__ float4 g_h[N_NODES * (D/4)];    // layer output
__device__ float  g_dinv[N_NODES];
__device__ int    g_cnt[N_NODES];          // in-degree histogram
__device__ int    g_off[N_NODES + 1];      // CSR offsets (exclusive)
__device__ int    g_fill[N_NODES];         // fill cursors
__device__ int    g_blk[NB1];              // scan partials
__device__ int    g_csr[N_EDGES];          // source node per CSR slot

// ---------------------------------------------------------------------------
// CSR build: histogram -> 3-stage exclusive scan -> fill
// ---------------------------------------------------------------------------
__global__ void hist_init_kernel() {
    int i = blockIdx.x * blockDim.x + threadIdx.x;
    if (i < N_NODES) g_cnt[i] = 0;
}

__global__ void hist_kernel(const int* __restrict__ coli) {
    int e = blockIdx.x * blockDim.x + threadIdx.x;
    if (e < N_EDGES) atomicAdd(&g_cnt[coli[e]], 1);
}

__global__ __launch_bounds__(256) void scan1_kernel() {
    __shared__ int sh[256];
    int tid = threadIdx.x;
    int base = blockIdx.x * SCAN_BS + tid * 4;
    int c[4];
    #pragma unroll
    for (int i = 0; i < 4; i++)
        c[i] = (base + i < N_NODES) ? g_cnt[base + i] : 0;
    int tot = c[0] + c[1] + c[2] + c[3];
    sh[tid] = tot;
    __syncthreads();
    #pragma unroll
    for (int o = 1; o < 256; o <<= 1) {
        int v = (tid >= o) ? sh[tid - o] : 0;
        __syncthreads();
        sh[tid] += v;
        __syncthreads();
    }
    int incl = sh[tid];
    int run = incl - tot;          // exclusive of this thread
    if (tid == 255) g_blk[blockIdx.x] = incl;
    #pragma unroll
    for (int i = 0; i < 4; i++) {
        if (base + i < N_NODES) g_off[base + i] = run;
        run += c[i];
    }
}

__global__ __launch_bounds__(256) void scan2_kernel() {
    __shared__ int sh[256];
    int tid = threadIdx.x;
    int v = (tid < NB1) ? g_blk[tid] : 0;
    sh[tid] = v;
    __syncthreads();
    #pragma unroll
    for (int o = 1; o < 256; o <<= 1) {
        int u = (tid >= o) ? sh[tid - o] : 0;
        __syncthreads();
        sh[tid] += u;
        __syncthreads();
    }
    if (tid < NB1) g_blk[tid] = sh[tid] - v;   // exclusive
}

__global__ void scan3_kernel() {
    int i = blockIdx.x * blockDim.x + threadIdx.x;
    if (i < N_NODES) {
        int off = g_off[i] + g_blk[i >> 10];
        g_off[i] = off;
        g_fill[i] = off;
        g_dinv[i] = rsqrtf((float)(g_cnt[i] + 1));   // +1 self loop
        if (i == 0) g_off[N_NODES] = N_EDGES;
    }
}

__global__ void fill_kernel(const int* __restrict__ rowi,
                            const int* __restrict__ coli) {
    int e = blockIdx.x * blockDim.x + threadIdx.x;
    if (e < N_EDGES) {
        int c = coli[e];
        int pos = atomicAdd(&g_fill[c], 1);
        g_csr[pos] = rowi[e];
    }
}

// ---------------------------------------------------------------------------
// GEMM: t' = (in @ W) * dinv.  Block = 256 threads, 64-node tile.
// Thread = (node-quad nq, feature group jg); 16 independent FMA chains.
// in == nullptr -> read previous layer output g_h.
// ---------------------------------------------------------------------------
#define XPAD 68

__global__ __launch_bounds__(256) void gemm_kernel(const float* __restrict__ in,
                                                   const float* __restrict__ W) {
    __shared__ float4 sW[D * (D/4)];
    __shared__ float  sx[64 * XPAD];

    int tid = threadIdx.x;
    int node0 = blockIdx.x * 64;

    const float4* W4 = (const float4*)W;
    #pragma unroll
    for (int i = 0; i < 4; i++) sW[tid + 256 * i] = W4[tid + 256 * i];

    float4* sx4 = (float4*)sx;
    #pragma unroll
    for (int i = 0; i < 4; i++) {
        int g = tid + 256 * i;
        int r = g >> 4;
        int c4 = g & 15;
        int node = node0 + r;
        float4 v = make_float4(0.f, 0.f, 0.f, 0.f);
        if (node < N_NODES) {
            if (in) v = ((const float4*)in)[node * (D/4) + c4];
            else    v = g_h[node * (D/4) + c4];
        }
        sx4[r * (XPAD/4) + c4] = v;
    }
    __syncthreads();

    int jg = tid & 15;
    int nq = tid >> 4;

    float4 acc[4];
    #pragma unroll
    for (int i = 0; i < 4; i++) acc[i] = make_float4(0.f, 0.f, 0.f, 0.f);

    #pragma unroll 8
    for (int k = 0; k < D; k++) {
        float4 w = sW[k * (D/4) + jg];
        #pragma unroll
        for (int i = 0; i < 4; i++) {
            float xv = sx[(nq * 4 + i) * XPAD + k];
            acc[i].x += xv * w.x;
            acc[i].y += xv * w.y;
            acc[i].z += xv * w.z;
            acc[i].w += xv * w.w;
        }
    }

    #pragma unroll
    for (int i = 0; i < 4; i++) {
        int node = node0 + nq * 4 + i;
        if (node < N_NODES) {
            float dv = g_dinv[node];
            float4 a = acc[i];
            a.x *= dv; a.y *= dv; a.z *= dv; a.w *= dv;
            g_t[node * (D/4) + jg] = a;
        }
    }
}

// ---------------------------------------------------------------------------
// Aggregate (pull-mode, no atomics) + fused BN/ReLU epilogue.
// 16 threads per node (one float4 lane each), 16 nodes per 256-thread block.
// last!=0: also compute out[node] = dot(h, lin_w) + lin_b instead of g_h.
// ---------------------------------------------------------------------------
__global__ __launch_bounds__(256) void aggregate_kernel(
        const float* __restrict__ b,
        const float* __restrict__ gamma,
        const float* __restrict__ beta,
        const float* __restrict__ mean,
        const float* __restrict__ var,
        const float* __restrict__ lin_w,
        const float* __restrict__ lin_b,
        float* __restrict__ out,
        int last) {
    int t = blockIdx.x * blockDim.x + threadIdx.x;
    int node = t >> 4;
    int sub = t & 15;
    if (node >= N_NODES) return;

    int s = g_off[node];
    int e = g_off[node + 1];

    float4 acc = g_t[node * (D/4) + sub];   // self loop (already dinv-scaled)

    int j = s;
    for (; j + 4 <= e; j += 4) {
        int n0 = __ldg(&g_csr[j + 0]);
        int n1 = __ldg(&g_csr[j + 1]);
        int n2 = __ldg(&g_csr[j + 2]);
        int n3 = __ldg(&g_csr[j + 3]);
        float4 v0 = g_t[n0 * (D/4) + sub];
        float4 v1 = g_t[n1 * (D/4) + sub];
        float4 v2 = g_t[n2 * (D/4) + sub];
        float4 v3 = g_t[n3 * (D/4) + sub];
        v0.x += v1.x; v0.y += v1.y; v0.z += v1.z; v0.w += v1.w;
        v2.x += v3.x; v2.y += v3.y; v2.z += v3.z; v2.w += v3.w;
        acc.x += v0.x + v2.x;
        acc.y += v0.y + v2.y;
        acc.z += v0.z + v2.z;
        acc.w += v0.w + v2.w;
    }
    for (; j < e; j++) {
        int n = __ldg(&g_csr[j]);
        float4 v = g_t[n * (D/4) + sub];
        acc.x += v.x; acc.y += v.y; acc.z += v.z; acc.w += v.w;
    }

    float dv = g_dinv[node];
    float4 bb = ((const float4*)b)[sub];
    float4 gm = ((const float4*)gamma)[sub];
    float4 bt = ((const float4*)beta)[sub];
    float4 mn = ((const float4*)mean)[sub];
    float4 vr = ((const float4*)var)[sub];

    float4 h;
    h.x = fmaxf(0.f, (acc.x * dv + bb.x - mn.x) * rsqrtf(vr.x + BN_EPS) * gm.x + bt.x);
    h.y = fmaxf(0.f, (acc.y * dv + bb.y - mn.y) * rsqrtf(vr.y + BN_EPS) * gm.y + bt.y);
    h.z = fmaxf(0.f, (acc.z * dv + bb.z - mn.z) * rsqrtf(vr.z + BN_EPS) * gm.z + bt.z);
    h.w = fmaxf(0.f, (acc.w * dv + bb.w - mn.w) * rsqrtf(vr.w + BN_EPS) * gm.w + bt.w);

    if (!last) {
        g_h[node * (D/4) + sub] = h;
    } else {
        float4 w = ((const float4*)lin_w)[sub];
        float dot = h.x * w.x + h.y * w.y + h.z * w.z + h.w * w.w;
        #pragma unroll
        for (int o = 8; o; o >>= 1)
            dot += __shfl_down_sync(0xFFFFFFFFu, dot, o, 16);
        if (sub == 0) out[node] = dot + lin_b[0];
    }
}

// ---------------------------------------------------------------------------
extern "C" void kernel_launch(void* const* d_in, const int* in_sizes, int n_in,
                              void* d_out, int out_size) {
    const float* x        = (const float*)d_in[0];
    const int*   ei       = (const int*)  d_in[1];   // [2, E]
    const float* Ws       = (const float*)d_in[2];   // [3, 64, 64]
    const float* bs       = (const float*)d_in[3];
    const float* gammas   = (const float*)d_in[4];
    const float* betas    = (const float*)d_in[5];
    const float* means    = (const float*)d_in[6];
    const float* variances= (const float*)d_in[7];
    const float* lin_w    = (const float*)d_in[8];
    const float* lin_b    = (const float*)d_in[9];

    const int* rowi = ei;
    const int* coli = ei + N_EDGES;

    // CSR build (per call; no cross-call caching)
    hist_init_kernel<<<(N_NODES + 255) / 256, 256>>>();
    hist_kernel<<<(N_EDGES + 255) / 256, 256>>>(coli);
    scan1_kernel<<<NB1, 256>>>();
    scan2_kernel<<<1, 256>>>();
    scan3_kernel<<<(N_NODES + 255) / 256, 256>>>();
    fill_kernel<<<(N_EDGES + 255) / 256, 256>>>(rowi, coli);

    const int gemm_blocks = (N_NODES + 63) / 64;
    const int agg_blocks = (N_NODES * 16 + 255) / 256;

    for (int l = 0; l < 3; l++) {
        const float* in = (l == 0) ? x : nullptr;   // nullptr -> g_h
        gemm_kernel<<<gemm_blocks, 256>>>(in, Ws + l * D * D);
        aggregate_kernel<<<agg_blocks, 256>>>(bs + l * D, gammas + l * D,
                                              betas + l * D, means + l * D,
                                              variances + l * D,
                                              lin_w, lin_b, (float*)d_out,
                                              (l == 2) ? 1 : 0);
    }
}